// round 6
// baseline (speedup 1.0000x reference)
#include <cuda_runtime.h>
#include <math.h>

#define NROWS 8192
#define DIM   128
#define MFEAT 128
#define NB    64

#define PHI_EPS  1e-4f
#define NORM_EPS 1e-8f
#define INV_D4   0.29730177875068026f   // 128^-0.25
#define INV_SQM  0.08838834764831845f   // 1/sqrt(128)

typedef unsigned long long ull;

// ---- device scratch (no allocs allowed) ----
__device__ float g_Qp[NROWS * MFEAT];
__device__ float g_EK[NROWS * MFEAT];       // exp(U_K - h)
__device__ float g_S[NB * MFEAT * DIM];
__device__ float g_Ksum[NB * MFEAT];
__device__ int   g_segmax[NB];              // float bits, init 0 == clamp at 0.0f
__device__ int   g_segstart[NB];
__device__ int   g_segend[NB];
__device__ int   g_is64;

// ---- packed f32x2 helpers (Blackwell) ----
__device__ __forceinline__ ull pack2(float x, float y) {
    ull r; asm("mov.b64 %0, {%1, %2};" : "=l"(r) : "f"(x), "f"(y)); return r;
}
__device__ __forceinline__ void unpack2(ull v, float& x, float& y) {
    asm("mov.b64 {%0, %1}, %2;" : "=f"(x), "=f"(y) : "l"(v));
}
__device__ __forceinline__ ull ffma2(ull a, ull b, ull c) {
    ull d; asm("fma.rn.f32x2 %0, %1, %2, %3;" : "=l"(d) : "l"(a), "l"(b), "l"(c));
    return d;
}

__device__ __forceinline__ int get_seg(const int* __restrict__ segp, int i) {
    return g_is64 ? segp[2 * i] : segp[i];
}

// ---------------------------------------------------------------------------
// Segment bounds from sorted batch_seg (boundary scan, no atomics) + segmax
// init + int64/int32 detection.
// ---------------------------------------------------------------------------
__global__ void __launch_bounds__(256)
bounds_kernel(const int* __restrict__ segp)
{
    __shared__ int s_is64;
    if (threadIdx.x == 0) {
        s_is64 = (segp[4097] == 0 && segp[4099] == 0 && segp[4101] == 0) ? 1 : 0;
        if (blockIdx.x == 0) g_is64 = s_is64;
    }
    __syncthreads();
    int is64 = s_is64;

    if (blockIdx.x == 0 && threadIdx.x < NB)
        g_segmax[threadIdx.x] = 0;          // float 0.0f bits == clamp at 0

    int i = blockIdx.x * blockDim.x + threadIdx.x;
    if (i < NROWS) {
        int cur  = is64 ? segp[2 * i] : segp[i];
        int prev = (i == 0) ? -1
                            : (is64 ? segp[2 * (i - 1)] : segp[i - 1]);
        for (int b = prev + 1; b <= cur; b++) g_segstart[b] = i;
        int nxt = (i == NROWS - 1) ? NB
                                   : (is64 ? segp[2 * (i + 1)] : segp[i + 1]);
        for (int b = cur; b < nxt; b++) g_segend[b] = i + 1;
        if (i == NROWS - 1)
            for (int b = cur + 1; b < NB; b++) g_segstart[b] = NROWS;
    }
}

// ---------------------------------------------------------------------------
// Fused Q/K feature kernel. grid = 2*(NROWS/32); first half Q, second half K.
// ---------------------------------------------------------------------------
__global__ void __launch_bounds__(256)
u_kernel(const float* __restrict__ Qin, const float* __restrict__ Kin,
         const float* __restrict__ omega, const int* __restrict__ segp)
{
    __shared__ __align__(16) float xs[128][32];      // [k][row]
    __shared__ __align__(16) float ws[16][128][2];   // [kk][m][dup]
    __shared__ float hsum[32];

    const int NBQ = NROWS / 32;
    bool isQ = blockIdx.x < NBQ;
    const float* X = isQ ? Qin : Kin;
    int row0 = (isQ ? blockIdx.x : blockIdx.x - NBQ) * 32;

    int t    = threadIdx.x;
    int lane = t & 31;
    int wrp  = t >> 5;

    if (t < 32) hsum[t] = 0.0f;
    __syncthreads();

    {
        int row = t & 31;
        int kqb = t >> 5;
        float ss = 0.0f;
#pragma unroll
        for (int it = 0; it < 4; it++) {
            int kq = kqb + 8 * it;
            float4 xv = *(const float4*)(X + (row0 + row) * DIM + kq * 4);
            xv.x *= INV_D4; xv.y *= INV_D4; xv.z *= INV_D4; xv.w *= INV_D4;
            xs[kq * 4 + 0][row] = xv.x;
            xs[kq * 4 + 1][row] = xv.y;
            xs[kq * 4 + 2][row] = xv.z;
            xs[kq * 4 + 3][row] = xv.w;
            ss += xv.x * xv.x + xv.y * xv.y + xv.z * xv.z + xv.w * xv.w;
        }
        atomicAdd(&hsum[row], ss);
    }

    ull acc[4][2];          // [mi][rowpair]
#pragma unroll
    for (int mi = 0; mi < 4; mi++) { acc[mi][0] = 0ull; acc[mi][1] = 0ull; }

#pragma unroll 1
    for (int kc = 0; kc < 8; kc++) {
        __syncthreads();
        {
#pragma unroll
            for (int it = 0; it < 2; it++) {
                int kk = wrp * 2 + it;
#pragma unroll
                for (int q = 0; q < 4; q++) {
                    int m = lane + 32 * q;
                    float w = omega[(kc * 16 + kk) * MFEAT + m];
                    *(float2*)&ws[kk][m][0] = make_float2(w, w);
                }
            }
        }
        __syncthreads();
#pragma unroll
        for (int kk = 0; kk < 16; kk++) {
            int k = kc * 16 + kk;
            float4 xq = *(const float4*)&xs[k][wrp * 4];   // 4 rows broadcast
            ull x01 = pack2(xq.x, xq.y);
            ull x23 = pack2(xq.z, xq.w);
#pragma unroll
            for (int mi = 0; mi < 4; mi++) {
                ull wd = *(const ull*)&ws[kk][lane + 32 * mi][0];
                acc[mi][0] = ffma2(x01, wd, acc[mi][0]);
                acc[mi][1] = ffma2(x23, wd, acc[mi][1]);
            }
        }
    }
    __syncthreads();

    float u[4][4];
#pragma unroll
    for (int mi = 0; mi < 4; mi++) {
        unpack2(acc[mi][0], u[0][mi], u[1][mi]);
        unpack2(acc[mi][1], u[2][mi], u[3][mi]);
    }

#pragma unroll
    for (int j = 0; j < 4; j++) {
        int rloc = wrp * 4 + j;
        int row  = row0 + rloc;
        float mx = fmaxf(fmaxf(u[j][0], u[j][1]), fmaxf(u[j][2], u[j][3]));
#pragma unroll
        for (int o = 16; o > 0; o >>= 1)
            mx = fmaxf(mx, __shfl_xor_sync(0xffffffffu, mx, o));
        float h = 0.5f * hsum[rloc];

        if (isQ) {
#pragma unroll
            for (int mi = 0; mi < 4; mi++)
                g_Qp[row * MFEAT + lane + 32 * mi] =
                    (__expf(u[j][mi] - h - mx) + PHI_EPS) * INV_SQM;
        } else {
#pragma unroll
            for (int mi = 0; mi < 4; mi++)
                g_EK[row * MFEAT + lane + 32 * mi] = __expf(u[j][mi] - h);
            if (lane == 0) {
                int s = get_seg(segp, row);
                atomicMax(&g_segmax[s], __float_as_int(mx));
            }
        }
    }
}

// ---------------------------------------------------------------------------
// S[b][m][d] = sum_rows Kp[row][m] * V[row][d];  Ksum[b][m] = sum_rows Kp.
// Kp reconstructed: kp = fma(E, exp(-smax)/sqrt(m), eps/sqrt(m)).
// ---------------------------------------------------------------------------
__global__ void __launch_bounds__(128)
s_kernel(const float* __restrict__ V)
{
    int mt  = blockIdx.x;     // 0..7
    int b   = blockIdx.y;     // 0..63
    int tid = threadIdx.x;
    int rs = g_segstart[b], re = g_segend[b];
    float smax = __int_as_float(g_segmax[b]);
    float cA = __expf(-smax) * INV_SQM;
    float cB = PHI_EPS * INV_SQM;

    __shared__ __align__(16) float kpc[16][16];

    ull acc[8];
#pragma unroll
    for (int j = 0; j < 8; j++) acc[j] = 0ull;
    float ksum = 0.0f;

    int rr_s = tid >> 3;          // staging row 0..15
    int m2   = (tid & 7) * 2;     // staging m pair

    int row = rs;
    int nfull = (re - rs) >> 4;

    float2 e;
    if (nfull > 0)
        e = *(const float2*)(g_EK + (row + rr_s) * MFEAT + mt * 16 + m2);

    for (int c = 0; c < nfull; c++, row += 16) {
        float2 kp;
        kp.x = fmaf(e.x, cA, cB);
        kp.y = fmaf(e.y, cA, cB);
        *(float2*)&kpc[rr_s][m2] = kp;
        __syncthreads();
        if (c + 1 < nfull)
            e = *(const float2*)(g_EK + (row + 16 + rr_s) * MFEAT + mt * 16 + m2);
#pragma unroll
        for (int rr = 0; rr < 16; rr++) {
            float v = V[(row + rr) * DIM + tid];
            ull vd = pack2(v, v);
            const ulonglong2* kp2 = (const ulonglong2*)&kpc[rr][0];
#pragma unroll
            for (int j = 0; j < 4; j++) {
                ulonglong2 kk2 = kp2[j];
                acc[2 * j]     = ffma2(kk2.x, vd, acc[2 * j]);
                acc[2 * j + 1] = ffma2(kk2.y, vd, acc[2 * j + 1]);
            }
        }
        if (tid < 16) {
#pragma unroll
            for (int rr = 0; rr < 16; rr++) ksum += kpc[rr][tid];
        }
        __syncthreads();
    }

    int ntail = re - row;
    if (ntail > 0) {
        if (rr_s < ntail) {
            float2 et = *(const float2*)(g_EK + (row + rr_s) * MFEAT + mt * 16 + m2);
            float2 kp;
            kp.x = fmaf(et.x, cA, cB);
            kp.y = fmaf(et.y, cA, cB);
            *(float2*)&kpc[rr_s][m2] = kp;
        }
        __syncthreads();
        for (int rr = 0; rr < ntail; rr++) {
            float v = V[(row + rr) * DIM + tid];
            ull vd = pack2(v, v);
            const ulonglong2* kp2 = (const ulonglong2*)&kpc[rr][0];
#pragma unroll
            for (int j = 0; j < 4; j++) {
                ulonglong2 kk2 = kp2[j];
                acc[2 * j]     = ffma2(kk2.x, vd, acc[2 * j]);
                acc[2 * j + 1] = ffma2(kk2.y, vd, acc[2 * j + 1]);
            }
        }
        if (tid < 16)
            for (int rr = 0; rr < ntail; rr++) ksum += kpc[rr][tid];
    }

#pragma unroll
    for (int j = 0; j < 8; j++) {
        float a0, a1;
        unpack2(acc[j], a0, a1);
        g_S[(b * MFEAT + mt * 16 + 2 * j)     * DIM + tid] = a0;
        g_S[(b * MFEAT + mt * 16 + 2 * j + 1) * DIM + tid] = a1;
    }
    if (tid < 16)
        g_Ksum[b * MFEAT + mt * 16 + tid] = ksum;
}

// ---------------------------------------------------------------------------
// Output phase, split into two kernels over the same grid (NROWS/16 blocks):
//   out_uniform:  blocks whose 16 rows all share one segment (vast majority).
//                 Straight-line register-tiled path, low regs, high occ.
//   out_boundary: blocks straddling a segment boundary (<= NB-1 blocks).
//                 Per-run tiled passes; high regs OK (one wave).
// ---------------------------------------------------------------------------

// shared helper: load Qp tile + segs, compute per-row norms
__device__ __forceinline__ void out_prologue(
    const int* __restrict__ segp, int row0, int tid, int lane, int wrp,
    float (*qs2f)[MFEAT][2], int* segs, float* norms)
{
#pragma unroll
    for (int r = 0; r < 16; r++)
        qs2f[r >> 1][tid][r & 1] = g_Qp[(row0 + r) * MFEAT + tid];
    if (tid < 16) segs[tid] = get_seg(segp, row0 + tid);
    __syncthreads();

#pragma unroll
    for (int rr = 0; rr < 4; rr++) {
        int r = wrp * 4 + rr;
        int s = segs[r];
        float p = 0.0f;
#pragma unroll
        for (int c = 0; c < 4; c++) {
            int m = c * 32 + lane;
            float q  = qs2f[r >> 1][m][r & 1];
            float ks = g_Ksum[s * MFEAT + m];
            p = fmaf(q, ks, p);
        }
#pragma unroll
        for (int o = 16; o > 0; o >>= 1)
            p += __shfl_xor_sync(0xffffffffu, p, o);
        if (lane == 0) norms[r] = p + NORM_EPS;
    }
    __syncthreads();
}

__global__ void __launch_bounds__(128)
out_uniform(const int* __restrict__ segp, float* __restrict__ out)
{
    __shared__ __align__(16) float qs2f[8][MFEAT][2];
    __shared__ int   segs[16];
    __shared__ float norms[16];

    int tid  = threadIdx.x;
    int lane = tid & 31;
    int wrp  = tid >> 5;
    int row0 = blockIdx.x * 16;

    // quick uniformity check before heavy prologue
    if (tid < 16) segs[tid] = get_seg(segp, row0 + tid);
    __syncthreads();
    if (segs[0] != segs[15]) return;     // boundary kernel owns this block
    __syncthreads();

    out_prologue(segp, row0, tid, lane, wrp, qs2f, segs, norms);

    const float* Srow = g_S + segs[0] * (MFEAT * DIM);

    ull acc2[8];
#pragma unroll
    for (int rp = 0; rp < 8; rp++) acc2[rp] = 0ull;

    ull sd[8];
#pragma unroll
    for (int j = 0; j < 8; j++) {
        float sv = Srow[j * DIM + tid];
        sd[j] = pack2(sv, sv);
    }

#pragma unroll
    for (int ms = 0; ms < 16; ms++) {
        int m0 = ms * 8;
        ull sdn[8];
        if (ms < 15) {
#pragma unroll
            for (int j = 0; j < 8; j++) {
                float sv = Srow[(m0 + 8 + j) * DIM + tid];
                sdn[j] = pack2(sv, sv);
            }
        }
#pragma unroll
        for (int rp = 0; rp < 8; rp++) {
            const ulonglong2* qp2 = (const ulonglong2*)&qs2f[rp][m0][0];
#pragma unroll
            for (int j2 = 0; j2 < 4; j2++) {
                ulonglong2 qq = qp2[j2];
                acc2[rp] = ffma2(qq.x, sd[2 * j2],     acc2[rp]);
                acc2[rp] = ffma2(qq.y, sd[2 * j2 + 1], acc2[rp]);
            }
        }
        if (ms < 15) {
#pragma unroll
            for (int j = 0; j < 8; j++) sd[j] = sdn[j];
        }
    }

#pragma unroll
    for (int rp = 0; rp < 8; rp++) {
        float a0, a1;
        unpack2(acc2[rp], a0, a1);
        out[(row0 + 2 * rp)     * DIM + tid] = a0 / norms[2 * rp];
        out[(row0 + 2 * rp + 1) * DIM + tid] = a1 / norms[2 * rp + 1];
    }
}

__global__ void __launch_bounds__(128)
out_boundary(const int* __restrict__ segp, float* __restrict__ out)
{
    __shared__ __align__(16) float qs2f[8][MFEAT][2];
    __shared__ int   segs[16];
    __shared__ float norms[16];

    int tid  = threadIdx.x;
    int lane = tid & 31;
    int wrp  = tid >> 5;
    int row0 = blockIdx.x * 16;

    if (tid < 16) segs[tid] = get_seg(segp, row0 + tid);
    __syncthreads();
    if (segs[0] == segs[15]) return;     // uniform kernel owns this block
    __syncthreads();

    out_prologue(segp, row0, tid, lane, wrp, qs2f, segs, norms);

    int rbeg = 0;
    while (rbeg < 16) {
        int s = segs[rbeg];
        int rend = rbeg + 1;
        while (rend < 16 && segs[rend] == s) rend++;

        const float* Srow = g_S + s * (MFEAT * DIM);

        ull acc2[8];
#pragma unroll
        for (int rp = 0; rp < 8; rp++) acc2[rp] = 0ull;

        ull sd[8];
#pragma unroll
        for (int j = 0; j < 8; j++) {
            float sv = Srow[j * DIM + tid];
            sd[j] = pack2(sv, sv);
        }

#pragma unroll
        for (int ms = 0; ms < 16; ms++) {
            int m0 = ms * 8;
            ull sdn[8];
            if (ms < 15) {
#pragma unroll
                for (int j = 0; j < 8; j++) {
                    float sv = Srow[(m0 + 8 + j) * DIM + tid];
                    sdn[j] = pack2(sv, sv);
                }
            }
#pragma unroll
            for (int rp = 0; rp < 8; rp++) {
                const ulonglong2* qp2 = (const ulonglong2*)&qs2f[rp][m0][0];
#pragma unroll
                for (int j2 = 0; j2 < 4; j2++) {
                    ulonglong2 qq = qp2[j2];
                    acc2[rp] = ffma2(qq.x, sd[2 * j2],     acc2[rp]);
                    acc2[rp] = ffma2(qq.y, sd[2 * j2 + 1], acc2[rp]);
                }
            }
            if (ms < 15) {
#pragma unroll
                for (int j = 0; j < 8; j++) sd[j] = sdn[j];
            }
        }

#pragma unroll
        for (int rp = 0; rp < 8; rp++) {
            float a0, a1;
            unpack2(acc2[rp], a0, a1);
            int r0 = 2 * rp, r1 = 2 * rp + 1;
            if (r0 >= rbeg && r0 < rend)
                out[(row0 + r0) * DIM + tid] = a0 / norms[r0];
            if (r1 >= rbeg && r1 < rend)
                out[(row0 + r1) * DIM + tid] = a1 / norms[r1];
        }

        rbeg = rend;
    }
}

extern "C" void kernel_launch(void* const* d_in, const int* in_sizes, int n_in,
                              void* d_out, int out_size)
{
    const float* Q     = (const float*)d_in[0];
    const float* K     = (const float*)d_in[1];
    const float* V     = (const float*)d_in[2];
    const float* omega = (const float*)d_in[3];
    const int*   seg   = (const int*)d_in[4];
    float* out = (float*)d_out;

    bounds_kernel<<<NROWS / 256, 256>>>(seg);
    u_kernel<<<2 * (NROWS / 32), 256>>>(Q, K, omega, seg);
    s_kernel<<<dim3(8, NB), 128>>>(V);
    out_uniform<<<NROWS / 16, 128>>>(seg, out);
    out_boundary<<<NROWS / 16, 128>>>(seg, out);
}

// round 7
// speedup vs baseline: 1.2172x; 1.2172x over previous
#include <cuda_runtime.h>
#include <math.h>

#define NROWS 8192
#define DIM   128
#define MFEAT 128
#define NB    64

#define PHI_EPS  1e-4f
#define NORM_EPS 1e-8f
#define INV_D4   0.29730177875068026f   // 128^-0.25
#define INV_SQM  0.08838834764831845f   // 1/sqrt(128)

typedef unsigned long long ull;

// ---- device scratch (no allocs allowed) ----
__device__ float g_Qp[NROWS * MFEAT];
__device__ float g_EK[NROWS * MFEAT];       // exp(U_K - h)
__device__ float g_S[NB * MFEAT * DIM];
__device__ float g_Ksum[NB * MFEAT];
__device__ int   g_segmax[NB];              // float bits, init 0 == clamp at 0.0f
__device__ int   g_segstart[NB];
__device__ int   g_segend[NB];
__device__ int   g_is64;

// ---- packed f32x2 helpers (Blackwell) ----
__device__ __forceinline__ ull pack2(float x, float y) {
    ull r; asm("mov.b64 %0, {%1, %2};" : "=l"(r) : "f"(x), "f"(y)); return r;
}
__device__ __forceinline__ void unpack2(ull v, float& x, float& y) {
    asm("mov.b64 {%0, %1}, %2;" : "=f"(x), "=f"(y) : "l"(v));
}
__device__ __forceinline__ ull ffma2(ull a, ull b, ull c) {
    ull d; asm("fma.rn.f32x2 %0, %1, %2, %3;" : "=l"(d) : "l"(a), "l"(b), "l"(c));
    return d;
}

__device__ __forceinline__ int get_seg(const int* __restrict__ segp, int i) {
    return g_is64 ? segp[2 * i] : segp[i];
}

// ---------------------------------------------------------------------------
// Segment bounds from sorted batch_seg (boundary scan, no atomics) + segmax
// init + int64/int32 detection.
// ---------------------------------------------------------------------------
__global__ void __launch_bounds__(256)
bounds_kernel(const int* __restrict__ segp)
{
    __shared__ int s_is64;
    if (threadIdx.x == 0) {
        s_is64 = (segp[4097] == 0 && segp[4099] == 0 && segp[4101] == 0) ? 1 : 0;
        if (blockIdx.x == 0) g_is64 = s_is64;
    }
    __syncthreads();
    int is64 = s_is64;

    if (blockIdx.x == 0 && threadIdx.x < NB)
        g_segmax[threadIdx.x] = 0;          // float 0.0f bits == clamp at 0

    int i = blockIdx.x * blockDim.x + threadIdx.x;
    if (i < NROWS) {
        int cur  = is64 ? segp[2 * i] : segp[i];
        int prev = (i == 0) ? -1
                            : (is64 ? segp[2 * (i - 1)] : segp[i - 1]);
        for (int b = prev + 1; b <= cur; b++) g_segstart[b] = i;
        int nxt = (i == NROWS - 1) ? NB
                                   : (is64 ? segp[2 * (i + 1)] : segp[i + 1]);
        for (int b = cur; b < nxt; b++) g_segend[b] = i + 1;
        if (i == NROWS - 1)
            for (int b = cur + 1; b < NB; b++) g_segstart[b] = NROWS;
    }
}

// ---------------------------------------------------------------------------
// Fused Q/K feature kernel. grid = 2*(NROWS/32); first half Q, second half K.
// ---------------------------------------------------------------------------
__global__ void __launch_bounds__(256)
u_kernel(const float* __restrict__ Qin, const float* __restrict__ Kin,
         const float* __restrict__ omega, const int* __restrict__ segp)
{
    __shared__ __align__(16) float xs[128][32];      // [k][row]
    __shared__ __align__(16) float ws[16][128][2];   // [kk][m][dup]
    __shared__ float hsum[32];

    const int NBQ = NROWS / 32;
    bool isQ = blockIdx.x < NBQ;
    const float* X = isQ ? Qin : Kin;
    int row0 = (isQ ? blockIdx.x : blockIdx.x - NBQ) * 32;

    int t    = threadIdx.x;
    int lane = t & 31;
    int wrp  = t >> 5;

    if (t < 32) hsum[t] = 0.0f;
    __syncthreads();

    {
        int row = t & 31;
        int kqb = t >> 5;
        float ss = 0.0f;
#pragma unroll
        for (int it = 0; it < 4; it++) {
            int kq = kqb + 8 * it;
            float4 xv = *(const float4*)(X + (row0 + row) * DIM + kq * 4);
            xv.x *= INV_D4; xv.y *= INV_D4; xv.z *= INV_D4; xv.w *= INV_D4;
            xs[kq * 4 + 0][row] = xv.x;
            xs[kq * 4 + 1][row] = xv.y;
            xs[kq * 4 + 2][row] = xv.z;
            xs[kq * 4 + 3][row] = xv.w;
            ss += xv.x * xv.x + xv.y * xv.y + xv.z * xv.z + xv.w * xv.w;
        }
        atomicAdd(&hsum[row], ss);
    }

    ull acc[4][2];          // [mi][rowpair]
#pragma unroll
    for (int mi = 0; mi < 4; mi++) { acc[mi][0] = 0ull; acc[mi][1] = 0ull; }

#pragma unroll 1
    for (int kc = 0; kc < 8; kc++) {
        __syncthreads();
        {
#pragma unroll
            for (int it = 0; it < 2; it++) {
                int kk = wrp * 2 + it;
#pragma unroll
                for (int q = 0; q < 4; q++) {
                    int m = lane + 32 * q;
                    float w = omega[(kc * 16 + kk) * MFEAT + m];
                    *(float2*)&ws[kk][m][0] = make_float2(w, w);
                }
            }
        }
        __syncthreads();
#pragma unroll
        for (int kk = 0; kk < 16; kk++) {
            int k = kc * 16 + kk;
            float4 xq = *(const float4*)&xs[k][wrp * 4];   // 4 rows broadcast
            ull x01 = pack2(xq.x, xq.y);
            ull x23 = pack2(xq.z, xq.w);
#pragma unroll
            for (int mi = 0; mi < 4; mi++) {
                ull wd = *(const ull*)&ws[kk][lane + 32 * mi][0];
                acc[mi][0] = ffma2(x01, wd, acc[mi][0]);
                acc[mi][1] = ffma2(x23, wd, acc[mi][1]);
            }
        }
    }
    __syncthreads();

    float u[4][4];
#pragma unroll
    for (int mi = 0; mi < 4; mi++) {
        unpack2(acc[mi][0], u[0][mi], u[1][mi]);
        unpack2(acc[mi][1], u[2][mi], u[3][mi]);
    }

#pragma unroll
    for (int j = 0; j < 4; j++) {
        int rloc = wrp * 4 + j;
        int row  = row0 + rloc;
        float mx = fmaxf(fmaxf(u[j][0], u[j][1]), fmaxf(u[j][2], u[j][3]));
#pragma unroll
        for (int o = 16; o > 0; o >>= 1)
            mx = fmaxf(mx, __shfl_xor_sync(0xffffffffu, mx, o));
        float h = 0.5f * hsum[rloc];

        if (isQ) {
#pragma unroll
            for (int mi = 0; mi < 4; mi++)
                g_Qp[row * MFEAT + lane + 32 * mi] =
                    (__expf(u[j][mi] - h - mx) + PHI_EPS) * INV_SQM;
        } else {
#pragma unroll
            for (int mi = 0; mi < 4; mi++)
                g_EK[row * MFEAT + lane + 32 * mi] = __expf(u[j][mi] - h);
            if (lane == 0) {
                int s = get_seg(segp, row);
                atomicMax(&g_segmax[s], __float_as_int(mx));
            }
        }
    }
}

// ---------------------------------------------------------------------------
// S[b][m][d] = sum_rows Kp[row][m] * V[row][d];  Ksum[b][m] = sum_rows Kp.
// Kp reconstructed: kp = fma(E, exp(-smax)/sqrt(m), eps/sqrt(m)).
// ---------------------------------------------------------------------------
__global__ void __launch_bounds__(128)
s_kernel(const float* __restrict__ V)
{
    int mt  = blockIdx.x;     // 0..7
    int b   = blockIdx.y;     // 0..63
    int tid = threadIdx.x;
    int rs = g_segstart[b], re = g_segend[b];
    float smax = __int_as_float(g_segmax[b]);
    float cA = __expf(-smax) * INV_SQM;
    float cB = PHI_EPS * INV_SQM;

    __shared__ __align__(16) float kpc[16][16];

    ull acc[8];
#pragma unroll
    for (int j = 0; j < 8; j++) acc[j] = 0ull;
    float ksum = 0.0f;

    int rr_s = tid >> 3;          // staging row 0..15
    int m2   = (tid & 7) * 2;     // staging m pair

    int row = rs;
    int nfull = (re - rs) >> 4;

    float2 e;
    if (nfull > 0)
        e = *(const float2*)(g_EK + (row + rr_s) * MFEAT + mt * 16 + m2);

    for (int c = 0; c < nfull; c++, row += 16) {
        float2 kp;
        kp.x = fmaf(e.x, cA, cB);
        kp.y = fmaf(e.y, cA, cB);
        *(float2*)&kpc[rr_s][m2] = kp;
        __syncthreads();
        if (c + 1 < nfull)
            e = *(const float2*)(g_EK + (row + 16 + rr_s) * MFEAT + mt * 16 + m2);
#pragma unroll
        for (int rr = 0; rr < 16; rr++) {
            float v = V[(row + rr) * DIM + tid];
            ull vd = pack2(v, v);
            const ulonglong2* kp2 = (const ulonglong2*)&kpc[rr][0];
#pragma unroll
            for (int j = 0; j < 4; j++) {
                ulonglong2 kk2 = kp2[j];
                acc[2 * j]     = ffma2(kk2.x, vd, acc[2 * j]);
                acc[2 * j + 1] = ffma2(kk2.y, vd, acc[2 * j + 1]);
            }
        }
        if (tid < 16) {
#pragma unroll
            for (int rr = 0; rr < 16; rr++) ksum += kpc[rr][tid];
        }
        __syncthreads();
    }

    int ntail = re - row;
    if (ntail > 0) {
        if (rr_s < ntail) {
            float2 et = *(const float2*)(g_EK + (row + rr_s) * MFEAT + mt * 16 + m2);
            float2 kp;
            kp.x = fmaf(et.x, cA, cB);
            kp.y = fmaf(et.y, cA, cB);
            *(float2*)&kpc[rr_s][m2] = kp;
        }
        __syncthreads();
        for (int rr = 0; rr < ntail; rr++) {
            float v = V[(row + rr) * DIM + tid];
            ull vd = pack2(v, v);
            const ulonglong2* kp2 = (const ulonglong2*)&kpc[rr][0];
#pragma unroll
            for (int j = 0; j < 4; j++) {
                ulonglong2 kk2 = kp2[j];
                acc[2 * j]     = ffma2(kk2.x, vd, acc[2 * j]);
                acc[2 * j + 1] = ffma2(kk2.y, vd, acc[2 * j + 1]);
            }
        }
        if (tid < 16)
            for (int rr = 0; rr < ntail; rr++) ksum += kpc[rr][tid];
    }

#pragma unroll
    for (int j = 0; j < 8; j++) {
        float a0, a1;
        unpack2(acc[j], a0, a1);
        g_S[(b * MFEAT + mt * 16 + 2 * j)     * DIM + tid] = a0;
        g_S[(b * MFEAT + mt * 16 + 2 * j + 1) * DIM + tid] = a1;
    }
    if (tid < 16)
        g_Ksum[b * MFEAT + mt * 16 + tid] = ksum;
}

// ---------------------------------------------------------------------------
// out[i][d] = (Qp[i] . S[seg][:, d]) / (Qp[i] . Ksum[seg] + eps)
// Grid (NB, 16): block (b, c) handles rows segstart[b]+16c .. +16 (clipped).
// Uniform segment per block BY CONSTRUCTION. 256 threads: ty = m-half (0/1),
// tx = d. Each half accumulates 64 of 128 m; halves combined through smem.
// ---------------------------------------------------------------------------
__global__ void __launch_bounds__(256)
out_kernel(float* __restrict__ out)
{
    int b  = blockIdx.x;
    int ck = blockIdx.y;
    int rs = g_segstart[b], re = g_segend[b];
    int r0 = rs + 16 * ck;
    if (r0 >= re) return;

    __shared__ __align__(16) float qs2f[8][MFEAT][2];  // [rowpair][m][which]
    __shared__ float norms[16];
    __shared__ __align__(16) float red[16][DIM];

    int tid  = threadIdx.x;
    int tx   = tid & 127;         // d
    int ty   = tid >> 7;          // m-half
    int lane = tid & 31;
    int wrp  = tid >> 5;          // 0..7

    // load Qp tile: ty half loads 8 of the 16 rows (clamped to segment end;
    // clamped rows produce garbage that is never stored)
#pragma unroll
    for (int rr = 0; rr < 8; rr++) {
        int r = ty * 8 + rr;
        int row = r0 + r;
        row = (row < re) ? row : (re - 1);
        qs2f[r >> 1][tx][r & 1] = g_Qp[row * MFEAT + tx];
    }
    __syncthreads();

    // norms: warp w handles rows 2w, 2w+1
#pragma unroll
    for (int rr = 0; rr < 2; rr++) {
        int r = wrp * 2 + rr;
        float p = 0.0f;
#pragma unroll
        for (int cc = 0; cc < 4; cc++) {
            int m = cc * 32 + lane;
            p = fmaf(qs2f[r >> 1][m][r & 1], g_Ksum[b * MFEAT + m], p);
        }
#pragma unroll
        for (int o = 16; o > 0; o >>= 1)
            p += __shfl_xor_sync(0xffffffffu, p, o);
        if (lane == 0) norms[r] = p + NORM_EPS;
    }

    // main accumulation over this ty's m-half [ty*64, ty*64+64)
    const float* Srow = g_S + b * (MFEAT * DIM);
    int mbase = ty * 64;

    ull acc2[8];
#pragma unroll
    for (int rp = 0; rp < 8; rp++) acc2[rp] = 0ull;

    ull sd[8];
#pragma unroll
    for (int j = 0; j < 8; j++) {
        float sv = Srow[(mbase + j) * DIM + tx];
        sd[j] = pack2(sv, sv);
    }

#pragma unroll
    for (int ms = 0; ms < 8; ms++) {
        int m0 = mbase + ms * 8;
        ull sdn[8];
        if (ms < 7) {
#pragma unroll
            for (int j = 0; j < 8; j++) {
                float sv = Srow[(m0 + 8 + j) * DIM + tx];
                sdn[j] = pack2(sv, sv);
            }
        }
#pragma unroll
        for (int rp = 0; rp < 8; rp++) {
            const ulonglong2* qp2 = (const ulonglong2*)&qs2f[rp][m0][0];
#pragma unroll
            for (int j2 = 0; j2 < 4; j2++) {
                ulonglong2 qq = qp2[j2];
                acc2[rp] = ffma2(qq.x, sd[2 * j2],     acc2[rp]);
                acc2[rp] = ffma2(qq.y, sd[2 * j2 + 1], acc2[rp]);
            }
        }
        if (ms < 7) {
#pragma unroll
            for (int j = 0; j < 8; j++) sd[j] = sdn[j];
        }
    }

    // combine halves through smem; ty==0 writes output
    if (ty == 1) {
#pragma unroll
        for (int rp = 0; rp < 8; rp++) {
            float a0, a1;
            unpack2(acc2[rp], a0, a1);
            red[2 * rp][tx]     = a0;
            red[2 * rp + 1][tx] = a1;
        }
    }
    __syncthreads();
    if (ty == 0) {
#pragma unroll
        for (int rp = 0; rp < 8; rp++) {
            float a0, a1;
            unpack2(acc2[rp], a0, a1);
            int r0i = 2 * rp, r1i = 2 * rp + 1;
            int row0i = r0 + r0i, row1i = r0 + r1i;
            if (row0i < re)
                out[row0i * DIM + tx] = (a0 + red[r0i][tx]) / norms[r0i];
            if (row1i < re)
                out[row1i * DIM + tx] = (a1 + red[r1i][tx]) / norms[r1i];
        }
    }
}

extern "C" void kernel_launch(void* const* d_in, const int* in_sizes, int n_in,
                              void* d_out, int out_size)
{
    const float* Q     = (const float*)d_in[0];
    const float* K     = (const float*)d_in[1];
    const float* V     = (const float*)d_in[2];
    const float* omega = (const float*)d_in[3];
    const int*   seg   = (const int*)d_in[4];
    float* out = (float*)d_out;

    bounds_kernel<<<NROWS / 256, 256>>>(seg);
    u_kernel<<<2 * (NROWS / 32), 256>>>(Q, K, omega, seg);
    s_kernel<<<dim3(8, NB), 128>>>(V);
    // 16 chunks covers segments up to 256 rows; expected max ~220 for B=64.
    // Safety: if a segment were longer, extra rows would be missed — use 32.
    out_kernel<<<dim3(NB, 32), 256>>>(out);
}